// round 5
// baseline (speedup 1.0000x reference)
#include <cuda_runtime.h>

#define BB 2
#define SS 2048
#define EE 1024
#define HH 16
#define DD 64
#define MTOK (BB*SS)      // 4096 tokens
#define NQKV (3*EE)       // 3072

typedef unsigned long long u64;

// Scratch (static device allocations — no cudaMalloc anywhere)
__device__ float g_qkv[(size_t)MTOK * NQKV];      // [token, 3E]  Q|K|V
__device__ float g_attnout[(size_t)MTOK * EE];    // pre-proj attention output
__device__ float g_l[BB*HH*SS];                   // per-row sum of exp(logit)

// ---------------------------------------------------------------------------
// Packed fp32x2 helpers (Blackwell FFMA2 — only reachable via PTX)
// ---------------------------------------------------------------------------
__device__ __forceinline__ u64 dupf(float x) {
    u64 r; asm("mov.b64 %0, {%1, %1};" : "=l"(r) : "f"(x)); return r;
}
__device__ __forceinline__ void fma2(u64& c, u64 a, u64 b) {
    asm("fma.rn.f32x2 %0, %1, %2, %0;" : "+l"(c) : "l"(a), "l"(b));
}
__device__ __forceinline__ float2 unpk(u64 v) {
    float2 r; asm("mov.b64 {%0, %1}, %2;" : "=f"(r.x), "=f"(r.y) : "l"(v)); return r;
}

// ---------------------------------------------------------------------------
// K1/K4: 128x128x16 SGEMM + bias, double-buffered smem, FFMA2 inner loop.
// C[M,N] = A[M,K] @ B[K,N] + bias.  M,N mult of 128; K mult of 16.
// Accumulators: 4 row-pairs x 8 cols of f32x2.
// ---------------------------------------------------------------------------
__global__ __launch_bounds__(256, 2) void gemm_bias_kernel(
    const float* __restrict__ A, const float* __restrict__ Bm,
    const float* __restrict__ bias, float* __restrict__ C,
    int N, int K)
{
    __shared__ __align__(16) float As[2][16][132];
    __shared__ __align__(16) float Bs[2][16][132];

    const int tid = threadIdx.x;
    const int tx = tid & 15, ty = tid >> 4;
    const int bx = blockIdx.x, by = blockIdx.y;

    const float* Aptr = A + (size_t)by * 128 * K;
    const float* Bptr = Bm + (size_t)bx * 128;

    u64 acc[4][8];
#pragma unroll
    for (int p = 0; p < 4; p++)
#pragma unroll
        for (int j = 0; j < 8; j++) acc[p][j] = 0ull;

    const int a_row = tid >> 2;          // 0..63
    const int a_col = (tid & 3) * 4;     // 0,4,8,12
    const int b_row = tid >> 5;          // 0..7
    const int b_col = (tid & 31) * 4;    // 0..124

    float4 a_reg[2], b_reg[2];
    // prologue: load chunk 0
#pragma unroll
    for (int rr = 0; rr < 2; rr++)
        a_reg[rr] = *(const float4*)(Aptr + (size_t)(a_row + rr * 64) * K + a_col);
#pragma unroll
    for (int rr = 0; rr < 2; rr++)
        b_reg[rr] = *(const float4*)(Bptr + (size_t)(b_row + rr * 8) * N + b_col);
#pragma unroll
    for (int rr = 0; rr < 2; rr++) {
        int row = a_row + rr * 64;
        As[0][a_col + 0][row] = a_reg[rr].x;
        As[0][a_col + 1][row] = a_reg[rr].y;
        As[0][a_col + 2][row] = a_reg[rr].z;
        As[0][a_col + 3][row] = a_reg[rr].w;
        *(float4*)&Bs[0][b_row + rr * 8][b_col] = b_reg[rr];
    }
    __syncthreads();

    const int nchunk = K >> 4;
    for (int c = 0; c < nchunk; c++) {
        const int cur = c & 1;
        if (c + 1 < nchunk) {
            const int k0 = (c + 1) * 16;
#pragma unroll
            for (int rr = 0; rr < 2; rr++)
                a_reg[rr] = *(const float4*)(Aptr + (size_t)(a_row + rr * 64) * K + k0 + a_col);
#pragma unroll
            for (int rr = 0; rr < 2; rr++)
                b_reg[rr] = *(const float4*)(Bptr + (size_t)(k0 + b_row + rr * 8) * N + b_col);
        }

#pragma unroll
        for (int kk = 0; kk < 16; kk++) {
            ulonglong2 ap0 = *(const ulonglong2*)&As[cur][kk][ty * 4];
            ulonglong2 ap1 = *(const ulonglong2*)&As[cur][kk][ty * 4 + 64];
            float4 bv0 = *(const float4*)&Bs[cur][kk][tx * 4];
            float4 bv1 = *(const float4*)&Bs[cur][kk][tx * 4 + 64];
            u64 ap[4] = {ap0.x, ap0.y, ap1.x, ap1.y};
            float bv[8] = {bv0.x, bv0.y, bv0.z, bv0.w, bv1.x, bv1.y, bv1.z, bv1.w};
#pragma unroll
            for (int j = 0; j < 8; j++) {
                u64 bd = dupf(bv[j]);
#pragma unroll
                for (int p = 0; p < 4; p++) fma2(acc[p][j], ap[p], bd);
            }
        }

        if (c + 1 < nchunk) {
            const int nxt = cur ^ 1;
#pragma unroll
            for (int rr = 0; rr < 2; rr++) {
                int row = a_row + rr * 64;
                As[nxt][a_col + 0][row] = a_reg[rr].x;
                As[nxt][a_col + 1][row] = a_reg[rr].y;
                As[nxt][a_col + 2][row] = a_reg[rr].z;
                As[nxt][a_col + 3][row] = a_reg[rr].w;
                *(float4*)&Bs[nxt][b_row + rr * 8][b_col] = b_reg[rr];
            }
        }
        __syncthreads();
    }

    // epilogue
#pragma unroll
    for (int p = 0; p < 4; p++) {
        const int rbase = (p < 2) ? (ty * 4 + 2 * p) : (64 + ty * 4 + 2 * (p - 2));
        float2 f[8];
#pragma unroll
        for (int j = 0; j < 8; j++) f[j] = unpk(acc[p][j]);
#pragma unroll
        for (int q = 0; q < 2; q++) {
            const int grow = by * 128 + rbase + q;
#pragma unroll
            for (int half = 0; half < 2; half++) {
                const int gcol = bx * 128 + tx * 4 + half * 64;
                float4 bs = *(const float4*)(bias + gcol);
                float4 o;
                o.x = (q ? f[half * 4 + 0].y : f[half * 4 + 0].x) + bs.x;
                o.y = (q ? f[half * 4 + 1].y : f[half * 4 + 1].x) + bs.y;
                o.z = (q ? f[half * 4 + 2].y : f[half * 4 + 2].x) + bs.z;
                o.w = (q ? f[half * 4 + 3].y : f[half * 4 + 3].x) + bs.w;
                *(float4*)(C + (size_t)grow * N + gcol) = o;
            }
        }
    }
}

// ---------------------------------------------------------------------------
// K2: per (bh, 128-row q-tile) compute causal logits, U = exp(s) (no max
// subtraction needed: |s| <~ 3), write U to weights buffer, accumulate row
// sums l.  128x128 score tiles, FFMA2 inner loop.
// ---------------------------------------------------------------------------
__global__ __launch_bounds__(256, 2) void scores_exp_kernel(float* __restrict__ out_w)
{
    extern __shared__ float sm2[];
    float* Qs = sm2;               // [64][132]  (prescaled by 1/8), [d][row]
    float* Ks = sm2 + 64 * 132;    // [64][132]  [d][col]

    const int qt = 15 - blockIdx.x;     // largest tiles first
    const int bh = blockIdx.y;
    const int b = bh >> 4, h = bh & 15;
    const int tid = threadIdx.x;
    const int tx = tid & 15, ty = tid >> 4;

    // stage Q tile (128 rows x 64 d), transposed, prescaled
    {
        const int r = tid >> 1;
        const int dbase = (tid & 1) * 32;
        const float* src = g_qkv + (size_t)(b * SS + qt * 128 + r) * NQKV + h * DD + dbase;
#pragma unroll
        for (int t = 0; t < 8; t++) {
            float4 v = *(const float4*)(src + t * 4);
            const int d = dbase + t * 4;
            Qs[(d + 0) * 132 + r] = v.x * 0.125f;
            Qs[(d + 1) * 132 + r] = v.y * 0.125f;
            Qs[(d + 2) * 132 + r] = v.z * 0.125f;
            Qs[(d + 3) * 132 + r] = v.w * 0.125f;
        }
    }

    float lpart[8];
#pragma unroll
    for (int i = 0; i < 8; i++) lpart[i] = 0.f;

    const size_t wbase = ((size_t)bh * SS + (size_t)qt * 128) * SS;

    for (int kt = 0; kt <= qt; kt++) {
        // stage K tile transposed
        {
            const int r = tid >> 1;
            const int dbase = (tid & 1) * 32;
            const float* src = g_qkv + (size_t)(b * SS + kt * 128 + r) * NQKV + EE + h * DD + dbase;
#pragma unroll
            for (int t = 0; t < 8; t++) {
                float4 v = *(const float4*)(src + t * 4);
                const int d = dbase + t * 4;
                Ks[(d + 0) * 132 + r] = v.x;
                Ks[(d + 1) * 132 + r] = v.y;
                Ks[(d + 2) * 132 + r] = v.z;
                Ks[(d + 3) * 132 + r] = v.w;
            }
        }
        __syncthreads();

        u64 s2[4][8];
#pragma unroll
        for (int p = 0; p < 4; p++)
#pragma unroll
            for (int j = 0; j < 8; j++) s2[p][j] = 0ull;

#pragma unroll 8
        for (int d = 0; d < 64; d++) {
            ulonglong2 qp0 = *(const ulonglong2*)&Qs[d * 132 + ty * 4];
            ulonglong2 qp1 = *(const ulonglong2*)&Qs[d * 132 + ty * 4 + 64];
            float4 kv0 = *(const float4*)&Ks[d * 132 + tx * 4];
            float4 kv1 = *(const float4*)&Ks[d * 132 + tx * 4 + 64];
            u64 qp[4] = {qp0.x, qp0.y, qp1.x, qp1.y};
            float kv[8] = {kv0.x, kv0.y, kv0.z, kv0.w, kv1.x, kv1.y, kv1.z, kv1.w};
#pragma unroll
            for (int j = 0; j < 8; j++) {
                u64 kd = dupf(kv[j]);
#pragma unroll
                for (int p = 0; p < 4; p++) fma2(s2[p][j], qp[p], kd);
            }
        }

        // epilogue for this tile: exp, causal mask on diag, store U, sum l
        const bool diag = (kt == qt);
        const int gk0 = kt * 128;
#pragma unroll
        for (int p = 0; p < 4; p++) {
            const int rloc0 = (p < 2) ? (ty * 4 + 2 * p) : (64 + ty * 4 + 2 * (p - 2));
            float2 f[8];
#pragma unroll
            for (int j = 0; j < 8; j++) f[j] = unpk(s2[p][j]);
#pragma unroll
            for (int q = 0; q < 2; q++) {
                const int rloc = rloc0 + q;
                float e[8];
#pragma unroll
                for (int j = 0; j < 8; j++) {
                    const int cloc = (j < 4) ? (tx * 4 + j) : (64 + tx * 4 + (j - 4));
                    float sv = q ? f[j].y : f[j].x;
                    float ev = __expf(sv);
                    if (diag && (cloc > rloc)) ev = 0.f;
                    e[j] = ev;
                }
                lpart[p * 2 + q] += ((e[0] + e[1]) + (e[2] + e[3]))
                                  + ((e[4] + e[5]) + (e[6] + e[7]));
                float* wr = out_w + wbase + (size_t)rloc * SS + gk0;
                *(float4*)(wr + tx * 4)      = make_float4(e[0], e[1], e[2], e[3]);
                *(float4*)(wr + tx * 4 + 64) = make_float4(e[4], e[5], e[6], e[7]);
            }
        }
        __syncthreads();
    }

    // reduce lpart over the 16 tx lanes, write l
#pragma unroll
    for (int i = 0; i < 8; i++) {
#pragma unroll
        for (int off = 8; off >= 1; off >>= 1)
            lpart[i] += __shfl_xor_sync(0xffffffffu, lpart[i], off);
    }
    if (tx == 0) {
#pragma unroll
        for (int i = 0; i < 8; i++) {
            const int p = i >> 1, q = i & 1;
            const int rloc = ((p < 2) ? (ty * 4 + 2 * p) : (64 + ty * 4 + 2 * (p - 2))) + q;
            g_l[bh * SS + qt * 128 + rloc] = lpart[i];
        }
    }
}

// ---------------------------------------------------------------------------
// K3: in-place W = U/l (and zero-fill the masked triangle), and
// O = (U @ V)/l -> g_attnout.  64-wide k chunks, FFMA2 inner loop.
// ---------------------------------------------------------------------------
__global__ __launch_bounds__(256, 2) void av_scale_kernel(float* __restrict__ out_w)
{
    extern __shared__ float sm3[];
    float* Us  = sm3;                   // [64 k][132 q] transposed U chunk
    float* Vs  = sm3 + 64 * 132;        // [64 k][68 d]
    float* ils = Vs + 64 * 68;          // [128] reciprocal row sums

    const int qt = 15 - blockIdx.x;
    const int bh = blockIdx.y;
    const int b = bh >> 4, h = bh & 15;
    const int tid = threadIdx.x;
    const int tx = tid & 15, ty = tid >> 4;

    if (tid < 128) ils[tid] = 1.0f / g_l[bh * SS + qt * 128 + tid];
    __syncthreads();

    u64 o2[4][4];
#pragma unroll
    for (int p = 0; p < 4; p++)
#pragma unroll
        for (int j = 0; j < 4; j++) o2[p][j] = 0ull;

    const size_t wbase = ((size_t)bh * SS + (size_t)qt * 128) * SS;
    const int nck = 2 * (qt + 1);       // number of 64-wide compute chunks

    for (int kc = 0; kc < nck; kc++) {
        // stage V chunk [64 k][64 d]
        {
            const int r = tid >> 2;
            const int dbase = (tid & 3) * 16;
            const float* src = g_qkv + (size_t)(b * SS + kc * 64 + r) * NQKV + 2 * EE + h * DD + dbase;
#pragma unroll
            for (int t = 0; t < 4; t++)
                *(float4*)&Vs[r * 68 + dbase + t * 4] = *(const float4*)(src + t * 4);
        }
        // stage U transposed into smem; write W = U*il back in place
        {
            const int q = tid >> 1;
            const int kbase = (tid & 1) * 32;
            const float il = ils[q];
            float* wrow = out_w + wbase + (size_t)q * SS + kc * 64 + kbase;
#pragma unroll
            for (int t = 0; t < 8; t++) {
                float4 u = *(const float4*)(wrow + t * 4);
                const int k = kbase + t * 4;
                Us[(k + 0) * 132 + q] = u.x;
                Us[(k + 1) * 132 + q] = u.y;
                Us[(k + 2) * 132 + q] = u.z;
                Us[(k + 3) * 132 + q] = u.w;
                *(float4*)(wrow + t * 4) =
                    make_float4(u.x * il, u.y * il, u.z * il, u.w * il);
            }
        }
        __syncthreads();

#pragma unroll 8
        for (int k = 0; k < 64; k++) {
            ulonglong2 up0 = *(const ulonglong2*)&Us[k * 132 + ty * 4];
            ulonglong2 up1 = *(const ulonglong2*)&Us[k * 132 + ty * 4 + 64];
            float4 v4 = *(const float4*)&Vs[k * 68 + tx * 4];
            u64 up[4] = {up0.x, up0.y, up1.x, up1.y};
            float vv[4] = {v4.x, v4.y, v4.z, v4.w};
#pragma unroll
            for (int j = 0; j < 4; j++) {
                u64 vd = dupf(vv[j]);
#pragma unroll
                for (int p = 0; p < 4; p++) fma2(o2[p][j], up[p], vd);
            }
        }
        __syncthreads();
    }

    // zero-fill fully masked chunks
    for (int kc = nck; kc < SS / 64; kc++) {
        const int q = tid >> 1;
        const int kbase = (tid & 1) * 32;
        float* wrow = out_w + wbase + (size_t)q * SS + kc * 64 + kbase;
        const float4 z = make_float4(0.f, 0.f, 0.f, 0.f);
#pragma unroll
        for (int t = 0; t < 8; t++) *(float4*)(wrow + t * 4) = z;
    }

    // epilogue: O * il -> g_attnout
#pragma unroll
    for (int p = 0; p < 4; p++) {
        const int rbase = (p < 2) ? (ty * 4 + 2 * p) : (64 + ty * 4 + 2 * (p - 2));
        float2 f[4];
#pragma unroll
        for (int j = 0; j < 4; j++) f[j] = unpk(o2[p][j]);
#pragma unroll
        for (int q = 0; q < 2; q++) {
            const int rloc = rbase + q;
            const float il = ils[rloc];
            float4 o;
            o.x = (q ? f[0].y : f[0].x) * il;
            o.y = (q ? f[1].y : f[1].x) * il;
            o.z = (q ? f[2].y : f[2].x) * il;
            o.w = (q ? f[3].y : f[3].x) * il;
            *(float4*)(g_attnout + (size_t)(b * SS + qt * 128 + rloc) * EE + h * DD + tx * 4) = o;
        }
    }
}

// ---------------------------------------------------------------------------
extern "C" void kernel_launch(void* const* d_in, const int* in_sizes, int n_in,
                              void* d_out, int out_size)
{
    const float* hidden = (const float*)d_in[0];   // [2,2048,1024]
    const float* w_attn = (const float*)d_in[1];   // [1024,3072]
    const float* b_attn = (const float*)d_in[2];   // [3072]
    const float* w_proj = (const float*)d_in[3];   // [1024,1024]
    const float* b_proj = (const float*)d_in[4];   // [1024]

    float* out = (float*)d_out;
    float* out_attn = out;                          // [2,2048,1024]
    float* out_w = out + (size_t)MTOK * EE;         // [2,16,2048,2048]

    float *qkv_ptr, *ao_ptr;
    cudaGetSymbolAddress((void**)&qkv_ptr, g_qkv);
    cudaGetSymbolAddress((void**)&ao_ptr, g_attnout);

    static int attr_done = 0;
    if (!attr_done) {
        cudaFuncSetAttribute(scores_exp_kernel,
                             cudaFuncAttributeMaxDynamicSharedMemorySize, 2 * 64 * 132 * 4);
        cudaFuncSetAttribute(av_scale_kernel,
                             cudaFuncAttributeMaxDynamicSharedMemorySize,
                             (64 * 132 + 64 * 68 + 128) * 4);
        attr_done = 1;
    }

    // K1: QKV = hidden @ Wqkv + b
    gemm_bias_kernel<<<dim3(NQKV / 128, MTOK / 128), 256>>>(
        hidden, w_attn, b_attn, qkv_ptr, NQKV, EE);

    // K2: U = exp(causal logits) -> weights buffer; row sums -> g_l
    scores_exp_kernel<<<dim3(SS / 128, BB * HH), 256, 2 * 64 * 132 * 4>>>(out_w);

    // K3: W = U/l in place (+ zero triangle); O = U@V / l
    av_scale_kernel<<<dim3(SS / 128, BB * HH), 256,
                      (64 * 132 + 64 * 68 + 128) * 4>>>(out_w);

    // K4: final projection
    gemm_bias_kernel<<<dim3(EE / 128, MTOK / 128), 256>>>(
        ao_ptr, w_proj, b_proj, out_attn, EE, EE);
}

// round 10
// speedup vs baseline: 1.4258x; 1.4258x over previous
#include <cuda_runtime.h>
#include <cuda_bf16.h>
#include <cstdint>

#define BB 2
#define SS 2048
#define EE 1024
#define HH 16
#define DD 64
#define MTOK (BB*SS)
#define NQKV (3*EE)

typedef unsigned long long u64;

__device__ float         g_qkv [(size_t)MTOK * NQKV];   // V region (f32) for K3
__device__ __nv_bfloat16 g_qkvh[(size_t)MTOK * NQKV];   // Q(scaled 1/8),K bf16 hi
__device__ __nv_bfloat16 g_qkvl[(size_t)MTOK * NQKV];   // lo
__device__ __nv_bfloat16 g_hh  [(size_t)MTOK * EE];
__device__ __nv_bfloat16 g_hl  [(size_t)MTOK * EE];
__device__ __nv_bfloat16 g_wqTh[(size_t)NQKV * EE];
__device__ __nv_bfloat16 g_wqTl[(size_t)NQKV * EE];
__device__ __nv_bfloat16 g_wpTh[(size_t)EE * EE];
__device__ __nv_bfloat16 g_wpTl[(size_t)EE * EE];
__device__ __nv_bfloat16 g_aoh [(size_t)MTOK * EE];
__device__ __nv_bfloat16 g_aol [(size_t)MTOK * EE];
__device__ float         g_l   [BB*HH*SS];

// ---- helpers ---------------------------------------------------------------
static __device__ __forceinline__ uint32_t smem_u32(const void* p) {
    uint32_t a;
    asm("{ .reg .u64 t; cvta.to.shared.u64 t, %1; cvt.u32.u64 %0, t; }" : "=r"(a) : "l"(p));
    return a;
}
static __device__ __forceinline__ void ldx4(uint32_t* r, uint32_t addr) {
    asm volatile("ldmatrix.sync.aligned.m8n8.x4.shared.b16 {%0,%1,%2,%3}, [%4];"
        : "=r"(r[0]), "=r"(r[1]), "=r"(r[2]), "=r"(r[3]) : "r"(addr));
}
static __device__ __forceinline__ void mma16816(float* c, const uint32_t* a, const uint32_t* b) {
    asm volatile("mma.sync.aligned.m16n8k16.row.col.f32.bf16.bf16.f32 "
        "{%0,%1,%2,%3}, {%4,%5,%6,%7}, {%8,%9}, {%0,%1,%2,%3};"
        : "+f"(c[0]), "+f"(c[1]), "+f"(c[2]), "+f"(c[3])
        : "r"(a[0]), "r"(a[1]), "r"(a[2]), "r"(a[3]), "r"(b[0]), "r"(b[1]));
}
#define CP16(d, s) asm volatile("cp.async.cg.shared.global [%0], [%1], 16;" :: "r"(d), "l"(s) : "memory")
#define CPC()      asm volatile("cp.async.commit_group;" ::: "memory")
#define CPW(n)     asm volatile("cp.async.wait_group %0;" :: "n"(n) : "memory")

// exp on the fma pipe: exp2 range reduction + Taylor deg-4 (rel err ~3e-5)
static __device__ __forceinline__ float exp_fast(float x) {
    float y = x * 1.4426950408889634f;
    float t = y + 12582912.0f;
    int   i = __float_as_int(t) - 0x4B400000;
    float f = y - (t - 12582912.0f);
    float p = 0.009618130f;
    p = fmaf(p, f, 0.055504109f);
    p = fmaf(p, f, 0.240226507f);
    p = fmaf(p, f, 0.693147181f);
    p = fmaf(p, f, 1.0f);
    return __int_as_float(__float_as_int(p) + (i << 23));
}

// ---- prep ------------------------------------------------------------------
__global__ void split_f32_kernel(const float* __restrict__ x,
                                 __nv_bfloat16* __restrict__ hi,
                                 __nv_bfloat16* __restrict__ lo) {
    size_t i = ((size_t)blockIdx.x * 256 + threadIdx.x) * 4;
    float4 v = *(const float4*)(x + i);
    float a[4] = {v.x, v.y, v.z, v.w};
#pragma unroll
    for (int j = 0; j < 4; j += 2) {
        __nv_bfloat16 h0 = __float2bfloat16_rn(a[j]);
        __nv_bfloat16 h1 = __float2bfloat16_rn(a[j+1]);
        __nv_bfloat16 l0 = __float2bfloat16_rn(a[j]   - __bfloat162float(h0));
        __nv_bfloat16 l1 = __float2bfloat16_rn(a[j+1] - __bfloat162float(h1));
        *(__nv_bfloat162*)(hi + i + j) = __halves2bfloat162(h0, h1);
        *(__nv_bfloat162*)(lo + i + j) = __halves2bfloat162(l0, l1);
    }
}

__global__ void transpose_split_kernel(const float* __restrict__ W,
                                       __nv_bfloat16* __restrict__ Th,
                                       __nv_bfloat16* __restrict__ Tl,
                                       int N, int K) {
    __shared__ float t[32][33];
    const int n0 = blockIdx.x * 32, k0 = blockIdx.y * 32;
    const int tx = threadIdx.x, ty = threadIdx.y;
    for (int r = ty; r < 32; r += 8)
        t[r][tx] = W[(size_t)(k0 + r) * N + n0 + tx];
    __syncthreads();
    for (int r = ty; r < 32; r += 8) {
        float v = t[tx][r];
        __nv_bfloat16 h = __float2bfloat16_rn(v);
        __nv_bfloat16 l = __float2bfloat16_rn(v - __bfloat162float(h));
        size_t o = (size_t)(n0 + r) * K + k0 + tx;
        Th[o] = h; Tl[o] = l;
    }
}

// ---- HMMA GEMM: C = (Ah+Al)[M,K] @ (Bth+Btl)[N,K]^T + bias -----------------
// 128x128 block, 8 warps (2x4), k-chunk 32, double-buffered cp.async.
// Padded smem rows: 40 bf16 (80B) -> conflict-free ldmatrix.
// mode 0: f32 out.  mode 1 (QKV): col<2048 -> bf16 hi/lo (Q scaled 1/8), else f32.
#define GARR 10240           // 128 rows * 80 B
#define GST  (4*GARR)        // one stage: Ah,Al,Bh,Bl
#define GSM_BYTES (2*GST)

__global__ void __launch_bounds__(256)
mm_gemm_kernel(const __nv_bfloat16* __restrict__ Ah, const __nv_bfloat16* __restrict__ Al,
               const __nv_bfloat16* __restrict__ Bth, const __nv_bfloat16* __restrict__ Btl,
               const float* __restrict__ bias, float* __restrict__ Cf,
               __nv_bfloat16* __restrict__ Ch, __nv_bfloat16* __restrict__ Cl,
               int N, int K, int mode)
{
    extern __shared__ char smp[];
    const uint32_t sm0 = smem_u32(smp);
    const int tid = threadIdx.x, wid = tid >> 5, lid = tid & 31;
    const int bx = blockIdx.x, by = blockIdx.y;
    const int wm = wid >> 2, wn = wid & 3;
    const int lrow = lid & 15, lcol = (lid >> 4) * 8;

    const __nv_bfloat16* gsrc[4] = {
        Ah  + (size_t)(by * 128) * K,
        Al  + (size_t)(by * 128) * K,
        Bth + (size_t)(bx * 128) * K,
        Btl + (size_t)(bx * 128) * K };

    float acc[4][4][4];
#pragma unroll
    for (int mi = 0; mi < 4; mi++)
#pragma unroll
        for (int nt = 0; nt < 4; nt++)
#pragma unroll
            for (int v = 0; v < 4; v++) acc[mi][nt][v] = 0.f;

    // stage chunk 0 -> buf 0
#pragma unroll
    for (int i = 0; i < 8; i++) {
        int g = tid + (i << 8);
        int a = g >> 9, row = (g >> 2) & 127, q = g & 3;
        CP16(sm0 + a * GARR + row * 80 + q * 16, gsrc[a] + (size_t)row * K + q * 8);
    }
    CPC();

    const int nchunk = K >> 5;
    for (int c = 0; c < nchunk; c++) {
        if (c + 1 < nchunk) {
            const int k0 = (c + 1) << 5;
            const uint32_t bb = (uint32_t)((c + 1) & 1) * GST;
#pragma unroll
            for (int i = 0; i < 8; i++) {
                int g = tid + (i << 8);
                int a = g >> 9, row = (g >> 2) & 127, q = g & 3;
                CP16(sm0 + bb + a * GARR + row * 80 + q * 16,
                     gsrc[a] + (size_t)row * K + k0 + q * 8);
            }
            CPC();
            CPW(1);
        } else {
            CPW(0);
        }
        __syncthreads();

        const uint32_t sb = sm0 + (uint32_t)(c & 1) * GST;
#pragma unroll
        for (int ks = 0; ks < 2; ks++) {
            uint32_t af[4][4], ag[4][4], bf_[4][2], bg[4][2];
            const uint32_t cofs = (uint32_t)(ks * 16 + lcol) * 2;
#pragma unroll
            for (int mi = 0; mi < 4; mi++) {
                uint32_t off = (uint32_t)(wm * 64 + mi * 16 + lrow) * 80 + cofs;
                ldx4(af[mi], sb + off);
                ldx4(ag[mi], sb + GARR + off);
            }
#pragma unroll
            for (int np = 0; np < 2; np++) {
                uint32_t off = (uint32_t)(wn * 32 + np * 16 + lrow) * 80 + cofs;
                uint32_t t[4];
                ldx4(t, sb + 2 * GARR + off);
                bf_[2*np][0] = t[0]; bf_[2*np][1] = t[2];
                bf_[2*np+1][0] = t[1]; bf_[2*np+1][1] = t[3];
                ldx4(t, sb + 3 * GARR + off);
                bg[2*np][0] = t[0]; bg[2*np][1] = t[2];
                bg[2*np+1][0] = t[1]; bg[2*np+1][1] = t[3];
            }
#pragma unroll
            for (int mi = 0; mi < 4; mi++)
#pragma unroll
                for (int nt = 0; nt < 4; nt++) {
                    mma16816(acc[mi][nt], af[mi], bf_[nt]);
                    mma16816(acc[mi][nt], af[mi], bg[nt]);
                    mma16816(acc[mi][nt], ag[mi], bf_[nt]);
                }
        }
        __syncthreads();
    }

    // epilogue
#pragma unroll
    for (int mi = 0; mi < 4; mi++) {
        const int r0 = by * 128 + wm * 64 + mi * 16 + (lid >> 2);
#pragma unroll
        for (int nt = 0; nt < 4; nt++) {
            const int gc = bx * 128 + wn * 32 + nt * 8 + 2 * (lid & 3);
            const float b0 = bias[gc], b1 = bias[gc + 1];
#pragma unroll
            for (int hf = 0; hf < 2; hf++) {
                const int r = r0 + hf * 8;
                float v0 = acc[mi][nt][hf * 2 + 0] + b0;
                float v1 = acc[mi][nt][hf * 2 + 1] + b1;
                if (mode == 0 || gc >= 2048) {
                    *(float2*)(Cf + (size_t)r * N + gc) = make_float2(v0, v1);
                } else {
                    const float sc = (gc < 1024) ? 0.125f : 1.0f;
                    v0 *= sc; v1 *= sc;
                    __nv_bfloat16 h0 = __float2bfloat16_rn(v0);
                    __nv_bfloat16 h1 = __float2bfloat16_rn(v1);
                    __nv_bfloat16 l0 = __float2bfloat16_rn(v0 - __bfloat162float(h0));
                    __nv_bfloat16 l1 = __float2bfloat16_rn(v1 - __bfloat162float(h1));
                    *(__nv_bfloat162*)(Ch + (size_t)r * N + gc) = __halves2bfloat162(h0, h1);
                    *(__nv_bfloat162*)(Cl + (size_t)r * N + gc) = __halves2bfloat162(l0, l1);
                }
            }
        }
    }
}

// ---- K2: HMMA QK^T + exp_fast epilogue -------------------------------------
// Per (bh, 128-q tile).  Q staged once, K tiles double-buffered.
// Padded rows: 72 bf16 (144B) -> conflict-free ldmatrix.
#define QBYTES 18432         // 128 rows * 144 B
#define KBASE  (2*QBYTES)
#define KST    (2*QBYTES)
#define SSM_BYTES (KBASE + 2*KST)

__global__ void __launch_bounds__(256)
mm_scores_kernel(float* __restrict__ out_w)
{
    extern __shared__ char smp[];
    const uint32_t sm0 = smem_u32(smp);
    __shared__ float ls[128];

    const int qt = 15 - blockIdx.x;
    const int bh = blockIdx.y;
    const int b = bh >> 4, h = bh & 15;
    const int tid = threadIdx.x, wid = tid >> 5, lid = tid & 31;
    const int wm = wid >> 2, wn = wid & 3;
    const int lrow = lid & 15, lcol = (lid >> 4) * 8;

    if (tid < 128) ls[tid] = 0.f;

    const __nv_bfloat16* qh = g_qkvh + (size_t)(b * SS + qt * 128) * NQKV + h * DD;
    const __nv_bfloat16* ql = g_qkvl + (size_t)(b * SS + qt * 128) * NQKV + h * DD;
    const __nv_bfloat16* kh = g_qkvh + (size_t)(b * SS) * NQKV + EE + h * DD;
    const __nv_bfloat16* kl = g_qkvl + (size_t)(b * SS) * NQKV + EE + h * DD;

    // stage Q (hi+lo) and K tile 0 in one commit group
#pragma unroll
    for (int i = 0; i < 8; i++) {
        int g = tid + (i << 8);
        int a = g >> 10, row = (g >> 3) & 127, q = g & 7;
        CP16(sm0 + a * QBYTES + row * 144 + q * 16,
             (a ? ql : qh) + (size_t)row * NQKV + q * 8);
    }
#pragma unroll
    for (int i = 0; i < 8; i++) {
        int g = tid + (i << 8);
        int a = g >> 10, row = (g >> 3) & 127, q = g & 7;
        CP16(sm0 + KBASE + a * QBYTES + row * 144 + q * 16,
             (a ? kl : kh) + (size_t)row * NQKV + q * 8);
    }
    CPC();

    float lsum[8];
#pragma unroll
    for (int i = 0; i < 8; i++) lsum[i] = 0.f;

    const size_t wbase = ((size_t)bh * SS + (size_t)qt * 128) * SS;

    for (int kt = 0; kt <= qt; kt++) {
        if (kt < qt) {
            const uint32_t bb = (uint32_t)((kt + 1) & 1) * KST;
#pragma unroll
            for (int i = 0; i < 8; i++) {
                int g = tid + (i << 8);
                int a = g >> 10, row = (g >> 3) & 127, q = g & 7;
                CP16(sm0 + KBASE + bb + a * QBYTES + row * 144 + q * 16,
                     (a ? kl : kh) + (size_t)((kt + 1) * 128 + row) * NQKV + q * 8);
            }
            CPC();
            CPW(1);
        } else {
            CPW(0);
        }
        __syncthreads();

        float acc[4][4][4];
#pragma unroll
        for (int mi = 0; mi < 4; mi++)
#pragma unroll
            for (int nt = 0; nt < 4; nt++)
#pragma unroll
                for (int v = 0; v < 4; v++) acc[mi][nt][v] = 0.f;

        const uint32_t kb = sm0 + KBASE + (uint32_t)(kt & 1) * KST;
#pragma unroll
        for (int ks = 0; ks < 4; ks++) {
            uint32_t af[4][4], ag[4][4], bf_[4][2], bg[4][2];
            const uint32_t cofs = (uint32_t)(ks * 16 + lcol) * 2;
#pragma unroll
            for (int mi = 0; mi < 4; mi++) {
                uint32_t off = (uint32_t)(wm * 64 + mi * 16 + lrow) * 144 + cofs;
                ldx4(af[mi], sm0 + off);
                ldx4(ag[mi], sm0 + QBYTES + off);
            }
#pragma unroll
            for (int np = 0; np < 2; np++) {
                uint32_t off = (uint32_t)(wn * 32 + np * 16 + lrow) * 144 + cofs;
                uint32_t t[4];
                ldx4(t, kb + off);
                bf_[2*np][0] = t[0]; bf_[2*np][1] = t[2];
                bf_[2*np+1][0] = t[1]; bf_[2*np+1][1] = t[3];
                ldx4(t, kb + QBYTES + off);
                bg[2*np][0] = t[0]; bg[2*np][1] = t[2];
                bg[2*np+1][0] = t[1]; bg[2*np+1][1] = t[3];
            }
#pragma unroll
            for (int mi = 0; mi < 4; mi++)
#pragma unroll
                for (int nt = 0; nt < 4; nt++) {
                    mma16816(acc[mi][nt], af[mi], bf_[nt]);
                    mma16816(acc[mi][nt], af[mi], bg[nt]);
                    mma16816(acc[mi][nt], ag[mi], bf_[nt]);
                }
        }

        // epilogue: exp + mask + store + row partial sums
        const bool diag = (kt == qt);
#pragma unroll
        for (int mi = 0; mi < 4; mi++)
#pragma unroll
            for (int hf = 0; hf < 2; hf++) {
                const int r = wm * 64 + mi * 16 + (lid >> 2) + hf * 8;
                float part = 0.f;
#pragma unroll
                for (int nt = 0; nt < 4; nt++) {
                    const int c = wn * 32 + nt * 8 + 2 * (lid & 3);
                    float e0 = exp_fast(acc[mi][nt][hf * 2 + 0]);
                    float e1 = exp_fast(acc[mi][nt][hf * 2 + 1]);
                    if (diag) {
                        if (c > r)     e0 = 0.f;
                        if (c + 1 > r) e1 = 0.f;
                    }
                    part += e0 + e1;
                    *(float2*)(out_w + wbase + (size_t)r * SS + kt * 128 + c) =
                        make_float2(e0, e1);
                }
                lsum[mi * 2 + hf] += part;
            }
        __syncthreads();
    }

    // reduce partial sums (lanes sharing lid>>2 hold same rows)
#pragma unroll
    for (int i = 0; i < 8; i++) {
        lsum[i] += __shfl_xor_sync(0xffffffffu, lsum[i], 1);
        lsum[i] += __shfl_xor_sync(0xffffffffu, lsum[i], 2);
    }
    if ((lid & 3) == 0) {
#pragma unroll
        for (int mi = 0; mi < 4; mi++)
#pragma unroll
            for (int hf = 0; hf < 2; hf++)
                atomicAdd(&ls[wm * 64 + mi * 16 + (lid >> 2) + hf * 8],
                          lsum[mi * 2 + hf]);
    }
    __syncthreads();
    if (tid < 128) g_l[bh * SS + qt * 128 + tid] = ls[tid];
}

// ---- K3: SIMT W=U/l + O=U@V/l (emits bf16 hi/lo attn-out) ------------------
__device__ __forceinline__ u64 dupf(float x) { u64 r; asm("mov.b64 %0, {%1, %1};" : "=l"(r) : "f"(x)); return r; }
__device__ __forceinline__ void fma2(u64& c, u64 a, u64 b) { asm("fma.rn.f32x2 %0, %1, %2, %0;" : "+l"(c) : "l"(a), "l"(b)); }
__device__ __forceinline__ float2 unpk(u64 v) { float2 r; asm("mov.b64 {%0, %1}, %2;" : "=f"(r.x), "=f"(r.y) : "l"(v)); return r; }

#define ASM_BYTES ((64*132 + 64*68 + 128) * 4)

__global__ __launch_bounds__(256, 2) void av_scale_kernel(float* __restrict__ out_w)
{
    extern __shared__ float sm3[];
    float* Us  = sm3;
    float* Vs  = sm3 + 64 * 132;
    float* ils = Vs + 64 * 68;

    const int qt = 15 - blockIdx.x;
    const int bh = blockIdx.y;
    const int b = bh >> 4, h = bh & 15;
    const int tid = threadIdx.x;
    const int tx = tid & 15, ty = tid >> 4;

    if (tid < 128) ils[tid] = 1.0f / g_l[bh * SS + qt * 128 + tid];
    __syncthreads();

    u64 o2[4][4];
#pragma unroll
    for (int p = 0; p < 4; p++)
#pragma unroll
        for (int j = 0; j < 4; j++) o2[p][j] = 0ull;

    const size_t wbase = ((size_t)bh * SS + (size_t)qt * 128) * SS;
    const int nck = 2 * (qt + 1);

    for (int kc = 0; kc < nck; kc++) {
        {
            const int r = tid >> 2;
            const int dbase = (tid & 3) * 16;
            const float* src = g_qkv + (size_t)(b * SS + kc * 64 + r) * NQKV + 2 * EE + h * DD + dbase;
#pragma unroll
            for (int t = 0; t < 4; t++)
                *(float4*)&Vs[r * 68 + dbase + t * 4] = *(const float4*)(src + t * 4);
        }
        {
            const int q = tid >> 1;
            const int kbase = (tid & 1) * 32;
            const float il = ils[q];
            float* wrow = out_w + wbase + (size_t)q * SS + kc * 64 + kbase;
#pragma unroll
            for (int t = 0; t < 8; t++) {
                float4 u = *(const float4*)(wrow + t * 4);
                const int k = kbase + t * 4;
                Us[(k + 0) * 132 + q] = u.x;
                Us[(k + 1) * 132 + q] = u.y;
                Us[(k + 2) * 132 + q] = u.z;
                Us[(k + 3) * 132 + q] = u.w;
                *(float4*)(wrow + t * 4) = make_float4(u.x * il, u.y * il, u.z * il, u.w * il);
            }
        }
        __syncthreads();

#pragma unroll 8
        for (int k = 0; k < 64; k++) {
            ulonglong2 up0 = *(const ulonglong2*)&Us[k * 132 + ty * 4];
            ulonglong2 up1 = *(const ulonglong2*)&Us[k * 132 + ty * 4 + 64];
            float4 v4 = *(const float4*)&Vs[k * 68 + tx * 4];
            u64 up[4] = {up0.x, up0.y, up1.x, up1.y};
            float vv[4] = {v4.x, v4.y, v4.z, v4.w};
#pragma unroll
            for (int j = 0; j < 4; j++) {
                u64 vd = dupf(vv[j]);
#pragma unroll
                for (int p = 0; p < 4; p++) fma2(o2[p][j], up[p], vd);
            }
        }
        __syncthreads();
    }

    for (int kc = nck; kc < SS / 64; kc++) {
        const int q = tid >> 1;
        const int kbase = (tid & 1) * 32;
        float* wrow = out_w + wbase + (size_t)q * SS + kc * 64 + kbase;
        const float4 z = make_float4(0.f, 0.f, 0.f, 0.f);
#pragma unroll
        for (int t = 0; t < 8; t++) *(float4*)(wrow + t * 4) = z;
    }

#pragma unroll
    for (int p = 0; p < 4; p++) {
        const int rbase = (p < 2) ? (ty * 4 + 2 * p) : (64 + ty * 4 + 2 * (p - 2));
        float2 f[4];
#pragma unroll
        for (int j = 0; j < 4; j++) f[j] = unpk(o2[p][j]);
#pragma unroll
        for (int q = 0; q < 2; q++) {
            const int rloc = rbase + q;
            const float il = ils[rloc];
            float v[4];
            v[0] = (q ? f[0].y : f[0].x) * il;
            v[1] = (q ? f[1].y : f[1].x) * il;
            v[2] = (q ? f[2].y : f[2].x) * il;
            v[3] = (q ? f[3].y : f[3].x) * il;
            const size_t base = (size_t)(b * SS + qt * 128 + rloc) * EE + h * DD + tx * 4;
#pragma unroll
            for (int j = 0; j < 4; j += 2) {
                __nv_bfloat16 h0 = __float2bfloat16_rn(v[j]);
                __nv_bfloat16 h1 = __float2bfloat16_rn(v[j+1]);
                __nv_bfloat16 l0 = __float2bfloat16_rn(v[j]   - __bfloat162float(h0));
                __nv_bfloat16 l1 = __float2bfloat16_rn(v[j+1] - __bfloat162float(h1));
                *(__nv_bfloat162*)(g_aoh + base + j) = __halves2bfloat162(h0, h1);
                *(__nv_bfloat162*)(g_aol + base + j) = __halves2bfloat162(l0, l1);
            }
        }
    }
}

// ---------------------------------------------------------------------------
extern "C" void kernel_launch(void* const* d_in, const int* in_sizes, int n_in,
                              void* d_out, int out_size)
{
    const float* hidden = (const float*)d_in[0];
    const float* w_attn = (const float*)d_in[1];
    const float* b_attn = (const float*)d_in[2];
    const float* w_proj = (const float*)d_in[3];
    const float* b_proj = (const float*)d_in[4];

    float* out = (float*)d_out;
    float* out_attn = out;
    float* out_w = out + (size_t)MTOK * EE;

    void *p_qkv, *p_qkvh, *p_qkvl, *p_hh, *p_hl, *p_wqTh, *p_wqTl, *p_wpTh, *p_wpTl, *p_aoh, *p_aol;
    cudaGetSymbolAddress(&p_qkv,  g_qkv);
    cudaGetSymbolAddress(&p_qkvh, g_qkvh);
    cudaGetSymbolAddress(&p_qkvl, g_qkvl);
    cudaGetSymbolAddress(&p_hh,   g_hh);
    cudaGetSymbolAddress(&p_hl,   g_hl);
    cudaGetSymbolAddress(&p_wqTh, g_wqTh);
    cudaGetSymbolAddress(&p_wqTl, g_wqTl);
    cudaGetSymbolAddress(&p_wpTh, g_wpTh);
    cudaGetSymbolAddress(&p_wpTl, g_wpTl);
    cudaGetSymbolAddress(&p_aoh,  g_aoh);
    cudaGetSymbolAddress(&p_aol,  g_aol);

    cudaFuncSetAttribute(mm_gemm_kernel,   cudaFuncAttributeMaxDynamicSharedMemorySize, GSM_BYTES);
    cudaFuncSetAttribute(mm_scores_kernel, cudaFuncAttributeMaxDynamicSharedMemorySize, SSM_BYTES);
    cudaFuncSetAttribute(av_scale_kernel,  cudaFuncAttributeMaxDynamicSharedMemorySize, ASM_BYTES);

    split_f32_kernel<<<(MTOK * EE) / 1024, 256>>>(hidden, (__nv_bfloat16*)p_hh, (__nv_bfloat16*)p_hl);
    transpose_split_kernel<<<dim3(NQKV / 32, EE / 32), dim3(32, 8)>>>(
        w_attn, (__nv_bfloat16*)p_wqTh, (__nv_bfloat16*)p_wqTl, NQKV, EE);
    transpose_split_kernel<<<dim3(EE / 32, EE / 32), dim3(32, 8)>>>(
        w_proj, (__nv_bfloat16*)p_wpTh, (__nv_bfloat16*)p_wpTl, EE, EE);

    // K1: QKV (HMMA)
    mm_gemm_kernel<<<dim3(NQKV / 128, MTOK / 128), 256, GSM_BYTES>>>(
        (const __nv_bfloat16*)p_hh, (const __nv_bfloat16*)p_hl,
        (const __nv_bfloat16*)p_wqTh, (const __nv_bfloat16*)p_wqTl,
        b_attn, (float*)p_qkv, (__nv_bfloat16*)p_qkvh, (__nv_bfloat16*)p_qkvl,
        NQKV, EE, 1);

    // K2: QK^T + exp (HMMA + exp_fast)
    mm_scores_kernel<<<dim3(SS / 128, BB * HH), 256, SSM_BYTES>>>(out_w);

    // K3: normalize W + O = U@V/l
    av_scale_kernel<<<dim3(SS / 128, BB * HH), 256, ASM_BYTES>>>(out_w);

    // K4: projection (HMMA)
    mm_gemm_kernel<<<dim3(EE / 128, MTOK / 128), 256, GSM_BYTES>>>(
        (const __nv_bfloat16*)p_aoh, (const __nv_bfloat16*)p_aol,
        (const __nv_bfloat16*)p_wpTh, (const __nv_bfloat16*)p_wpTl,
        b_proj, out_attn, (__nv_bfloat16*)0, (__nv_bfloat16*)0,
        EE, EE, 0);
}

// round 14
// speedup vs baseline: 1.8041x; 1.2654x over previous
#include <cuda_runtime.h>
#include <cuda_bf16.h>
#include <cstdint>

#define BB 2
#define SS 2048
#define EE 1024
#define HH 16
#define DD 64
#define MTOK (BB*SS)
#define NQKV (3*EE)

__device__ __nv_bfloat16 g_qkvh[(size_t)MTOK * NQKV];   // Q(1/8),K,V bf16 hi
__device__ __nv_bfloat16 g_qkvl[(size_t)MTOK * NQKV];   // lo
__device__ __nv_bfloat16 g_hh  [(size_t)MTOK * EE];
__device__ __nv_bfloat16 g_hl  [(size_t)MTOK * EE];
__device__ __nv_bfloat16 g_wqTh[(size_t)NQKV * EE];
__device__ __nv_bfloat16 g_wqTl[(size_t)NQKV * EE];
__device__ __nv_bfloat16 g_wpTh[(size_t)EE * EE];
__device__ __nv_bfloat16 g_wpTl[(size_t)EE * EE];
__device__ __nv_bfloat16 g_aoh [(size_t)MTOK * EE];
__device__ __nv_bfloat16 g_aol [(size_t)MTOK * EE];
__device__ float         g_l   [BB*HH*SS];

// ---- helpers ---------------------------------------------------------------
static __device__ __forceinline__ uint32_t smem_u32(const void* p) {
    uint32_t a;
    asm("{ .reg .u64 t; cvta.to.shared.u64 t, %1; cvt.u32.u64 %0, t; }" : "=r"(a) : "l"(p));
    return a;
}
static __device__ __forceinline__ void ldx4(uint32_t* r, uint32_t addr) {
    asm volatile("ldmatrix.sync.aligned.m8n8.x4.shared.b16 {%0,%1,%2,%3}, [%4];"
        : "=r"(r[0]), "=r"(r[1]), "=r"(r[2]), "=r"(r[3]) : "r"(addr));
}
static __device__ __forceinline__ void ldx4t(uint32_t* r, uint32_t addr) {
    asm volatile("ldmatrix.sync.aligned.m8n8.x4.trans.shared.b16 {%0,%1,%2,%3}, [%4];"
        : "=r"(r[0]), "=r"(r[1]), "=r"(r[2]), "=r"(r[3]) : "r"(addr));
}
static __device__ __forceinline__ void mma16816(float* c, const uint32_t* a, const uint32_t* b) {
    asm volatile("mma.sync.aligned.m16n8k16.row.col.f32.bf16.bf16.f32 "
        "{%0,%1,%2,%3}, {%4,%5,%6,%7}, {%8,%9}, {%0,%1,%2,%3};"
        : "+f"(c[0]), "+f"(c[1]), "+f"(c[2]), "+f"(c[3])
        : "r"(a[0]), "r"(a[1]), "r"(a[2]), "r"(a[3]), "r"(b[0]), "r"(b[1]));
}
#define CP16(d, s) asm volatile("cp.async.cg.shared.global [%0], [%1], 16;" :: "r"(d), "l"(s) : "memory")
#define CPC()      asm volatile("cp.async.commit_group;" ::: "memory")
#define CPW(n)     asm volatile("cp.async.wait_group %0;" :: "n"(n) : "memory")

static __device__ __forceinline__ float exp_fast(float x) {
    float y = x * 1.4426950408889634f;
    float t = y + 12582912.0f;
    int   i = __float_as_int(t) - 0x4B400000;
    float f = y - (t - 12582912.0f);
    float p = 0.009618130f;
    p = fmaf(p, f, 0.055504109f);
    p = fmaf(p, f, 0.240226507f);
    p = fmaf(p, f, 0.693147181f);
    p = fmaf(p, f, 1.0f);
    return __int_as_float(__float_as_int(p) + (i << 23));
}
static __device__ __forceinline__ __nv_bfloat162 split_hi(float a, float b,
                                                          float& ra, float& rb) {
    __nv_bfloat16 h0 = __float2bfloat16_rn(a);
    __nv_bfloat16 h1 = __float2bfloat16_rn(b);
    ra = a - __bfloat162float(h0);
    rb = b - __bfloat162float(h1);
    return __halves2bfloat162(h0, h1);
}

// ---- prep ------------------------------------------------------------------
__global__ void split_f32_kernel(const float* __restrict__ x,
                                 __nv_bfloat16* __restrict__ hi,
                                 __nv_bfloat16* __restrict__ lo) {
    size_t i = ((size_t)blockIdx.x * 256 + threadIdx.x) * 4;
    float4 v = *(const float4*)(x + i);
    float r0, r1;
    *(__nv_bfloat162*)(hi + i)     = split_hi(v.x, v.y, r0, r1);
    *(__nv_bfloat162*)(lo + i)     = __halves2bfloat162(__float2bfloat16_rn(r0), __float2bfloat16_rn(r1));
    *(__nv_bfloat162*)(hi + i + 2) = split_hi(v.z, v.w, r0, r1);
    *(__nv_bfloat162*)(lo + i + 2) = __halves2bfloat162(__float2bfloat16_rn(r0), __float2bfloat16_rn(r1));
}

__global__ void transpose_split_kernel(const float* __restrict__ W,
                                       __nv_bfloat16* __restrict__ Th,
                                       __nv_bfloat16* __restrict__ Tl,
                                       int N, int K) {
    __shared__ float t[32][33];
    const int n0 = blockIdx.x * 32, k0 = blockIdx.y * 32;
    const int tx = threadIdx.x, ty = threadIdx.y;
    for (int r = ty; r < 32; r += 8)
        t[r][tx] = W[(size_t)(k0 + r) * N + n0 + tx];
    __syncthreads();
    for (int r = ty; r < 32; r += 8) {
        float v = t[tx][r];
        __nv_bfloat16 h = __float2bfloat16_rn(v);
        __nv_bfloat16 l = __float2bfloat16_rn(v - __bfloat162float(h));
        size_t o = (size_t)(n0 + r) * K + k0 + tx;
        Th[o] = h; Tl[o] = l;
    }
}

// ---- HMMA GEMM v2: 3-stage pipeline, chunk 16, 1 sync/chunk ----------------
// C = (Ah+Al)[M,K] @ (Bth+Btl)[N,K]^T + bias.  128x128 block, 8 warps (2x4).
// 48B rows: granule 3r+s is a permutation mod 8 -> conflict-free ldmatrix.
// mode 0: f32 out.  mode 1 (QKV): bf16 hi/lo out (cols<1024 scaled 1/8).
#define GROW 48
#define GARR (128*GROW)      // 6144
#define GST  (4*GARR)        // 24576
#define GSM_BYTES (3*GST)    // 73728

__global__ void __launch_bounds__(256, 2)
mm_gemm_kernel(const __nv_bfloat16* __restrict__ Ah, const __nv_bfloat16* __restrict__ Al,
               const __nv_bfloat16* __restrict__ Bth, const __nv_bfloat16* __restrict__ Btl,
               const float* __restrict__ bias, float* __restrict__ Cf,
               __nv_bfloat16* __restrict__ Ch, __nv_bfloat16* __restrict__ Cl,
               int N, int K, int mode)
{
    extern __shared__ char smp[];
    const uint32_t sm0 = smem_u32(smp);
    const int tid = threadIdx.x, wid = tid >> 5, lid = tid & 31;
    const int bx = blockIdx.x, by = blockIdx.y;
    const int wm = wid >> 2, wn = wid & 3;
    const int lrow = lid & 15, lcol = (lid >> 4) * 8;

    const __nv_bfloat16* gsrc[4] = {
        Ah  + (size_t)(by * 128) * K,
        Al  + (size_t)(by * 128) * K,
        Bth + (size_t)(bx * 128) * K,
        Btl + (size_t)(bx * 128) * K };

    const int srow = tid >> 1, sq = tid & 1;

    float acc[4][4][4];
#pragma unroll
    for (int mi = 0; mi < 4; mi++)
#pragma unroll
        for (int nt = 0; nt < 4; nt++)
#pragma unroll
            for (int v = 0; v < 4; v++) acc[mi][nt][v] = 0.f;

#define GSTAGE(c) do { \
        const uint32_t bb_ = sm0 + (uint32_t)((c) % 3) * GST; \
        const int k0_ = (c) << 4; \
        _Pragma("unroll") \
        for (int a_ = 0; a_ < 4; a_++) \
            CP16(bb_ + a_ * GARR + srow * GROW + sq * 16, \
                 gsrc[a_] + (size_t)srow * K + k0_ + sq * 8); \
        CPC(); \
    } while (0)

    const int nchunk = K >> 4;
    GSTAGE(0);
    GSTAGE(1);

    for (int c = 0; c < nchunk; c++) {
        if (c + 1 < nchunk) { CPW(1); } else { CPW(0); }
        __syncthreads();
        if (c + 2 < nchunk) GSTAGE(c + 2);

        const uint32_t sb = sm0 + (uint32_t)(c % 3) * GST;
        uint32_t af[4][4], ag[4][4], bf_[4][2], bg[4][2];
#pragma unroll
        for (int mi = 0; mi < 4; mi++) {
            uint32_t off = (uint32_t)(wm * 64 + mi * 16 + lrow) * GROW + lcol * 2;
            ldx4(af[mi], sb + off);
            ldx4(ag[mi], sb + GARR + off);
        }
#pragma unroll
        for (int np = 0; np < 2; np++) {
            uint32_t off = (uint32_t)(wn * 32 + np * 16 + lrow) * GROW + lcol * 2;
            uint32_t t[4];
            ldx4(t, sb + 2 * GARR + off);
            bf_[2*np][0] = t[0]; bf_[2*np][1] = t[2];
            bf_[2*np+1][0] = t[1]; bf_[2*np+1][1] = t[3];
            ldx4(t, sb + 3 * GARR + off);
            bg[2*np][0] = t[0]; bg[2*np][1] = t[2];
            bg[2*np+1][0] = t[1]; bg[2*np+1][1] = t[3];
        }
#pragma unroll
        for (int mi = 0; mi < 4; mi++)
#pragma unroll
            for (int nt = 0; nt < 4; nt++) {
                mma16816(acc[mi][nt], af[mi], bf_[nt]);
                mma16816(acc[mi][nt], af[mi], bg[nt]);
                mma16816(acc[mi][nt], ag[mi], bf_[nt]);
            }
    }

    // epilogue
#pragma unroll
    for (int mi = 0; mi < 4; mi++) {
        const int r0 = by * 128 + wm * 64 + mi * 16 + (lid >> 2);
#pragma unroll
        for (int nt = 0; nt < 4; nt++) {
            const int gc = bx * 128 + wn * 32 + nt * 8 + 2 * (lid & 3);
            const float b0 = bias[gc], b1 = bias[gc + 1];
#pragma unroll
            for (int hf = 0; hf < 2; hf++) {
                const int r = r0 + hf * 8;
                float v0 = acc[mi][nt][hf * 2 + 0] + b0;
                float v1 = acc[mi][nt][hf * 2 + 1] + b1;
                if (mode == 0) {
                    *(float2*)(Cf + (size_t)r * N + gc) = make_float2(v0, v1);
                } else {
                    const float sc = (gc < 1024) ? 0.125f : 1.0f;
                    v0 *= sc; v1 *= sc;
                    float r0f, r1f;
                    *(__nv_bfloat162*)(Ch + (size_t)r * N + gc) = split_hi(v0, v1, r0f, r1f);
                    *(__nv_bfloat162*)(Cl + (size_t)r * N + gc) =
                        __halves2bfloat162(__float2bfloat16_rn(r0f), __float2bfloat16_rn(r1f));
                }
            }
        }
    }
#undef GSTAGE
}

// ---- K2: HMMA QK^T + exp_fast (unchanged from R10) -------------------------
#define QBYTES 18432
#define KBASE  (2*QBYTES)
#define KST    (2*QBYTES)
#define SSM_BYTES (KBASE + 2*KST)

__global__ void __launch_bounds__(256)
mm_scores_kernel(float* __restrict__ out_w)
{
    extern __shared__ char smp[];
    const uint32_t sm0 = smem_u32(smp);
    __shared__ float ls[128];

    const int qt = 15 - blockIdx.x;
    const int bh = blockIdx.y;
    const int b = bh >> 4, h = bh & 15;
    const int tid = threadIdx.x, wid = tid >> 5, lid = tid & 31;
    const int wm = wid >> 2, wn = wid & 3;
    const int lrow = lid & 15, lcol = (lid >> 4) * 8;

    if (tid < 128) ls[tid] = 0.f;

    const __nv_bfloat16* qh = g_qkvh + (size_t)(b * SS + qt * 128) * NQKV + h * DD;
    const __nv_bfloat16* ql = g_qkvl + (size_t)(b * SS + qt * 128) * NQKV + h * DD;
    const __nv_bfloat16* kh = g_qkvh + (size_t)(b * SS) * NQKV + EE + h * DD;
    const __nv_bfloat16* kl = g_qkvl + (size_t)(b * SS) * NQKV + EE + h * DD;

#pragma unroll
    for (int i = 0; i < 8; i++) {
        int g = tid + (i << 8);
        int a = g >> 10, row = (g >> 3) & 127, q = g & 7;
        CP16(sm0 + a * QBYTES + row * 144 + q * 16,
             (a ? ql : qh) + (size_t)row * NQKV + q * 8);
    }
#pragma unroll
    for (int i = 0; i < 8; i++) {
        int g = tid + (i << 8);
        int a = g >> 10, row = (g >> 3) & 127, q = g & 7;
        CP16(sm0 + KBASE + a * QBYTES + row * 144 + q * 16,
             (a ? kl : kh) + (size_t)row * NQKV + q * 8);
    }
    CPC();

    float lsum[8];
#pragma unroll
    for (int i = 0; i < 8; i++) lsum[i] = 0.f;

    const size_t wbase = ((size_t)bh * SS + (size_t)qt * 128) * SS;

    for (int kt = 0; kt <= qt; kt++) {
        if (kt < qt) {
            const uint32_t bb = (uint32_t)((kt + 1) & 1) * KST;
#pragma unroll
            for (int i = 0; i < 8; i++) {
                int g = tid + (i << 8);
                int a = g >> 10, row = (g >> 3) & 127, q = g & 7;
                CP16(sm0 + KBASE + bb + a * QBYTES + row * 144 + q * 16,
                     (a ? kl : kh) + (size_t)((kt + 1) * 128 + row) * NQKV + q * 8);
            }
            CPC();
            CPW(1);
        } else {
            CPW(0);
        }
        __syncthreads();

        float acc[4][4][4];
#pragma unroll
        for (int mi = 0; mi < 4; mi++)
#pragma unroll
            for (int nt = 0; nt < 4; nt++)
#pragma unroll
                for (int v = 0; v < 4; v++) acc[mi][nt][v] = 0.f;

        const uint32_t kb = sm0 + KBASE + (uint32_t)(kt & 1) * KST;
#pragma unroll
        for (int ks = 0; ks < 4; ks++) {
            uint32_t af[4][4], ag[4][4], bf_[4][2], bg[4][2];
            const uint32_t cofs = (uint32_t)(ks * 16 + lcol) * 2;
#pragma unroll
            for (int mi = 0; mi < 4; mi++) {
                uint32_t off = (uint32_t)(wm * 64 + mi * 16 + lrow) * 144 + cofs;
                ldx4(af[mi], sm0 + off);
                ldx4(ag[mi], sm0 + QBYTES + off);
            }
#pragma unroll
            for (int np = 0; np < 2; np++) {
                uint32_t off = (uint32_t)(wn * 32 + np * 16 + lrow) * 144 + cofs;
                uint32_t t[4];
                ldx4(t, kb + off);
                bf_[2*np][0] = t[0]; bf_[2*np][1] = t[2];
                bf_[2*np+1][0] = t[1]; bf_[2*np+1][1] = t[3];
                ldx4(t, kb + QBYTES + off);
                bg[2*np][0] = t[0]; bg[2*np][1] = t[2];
                bg[2*np+1][0] = t[1]; bg[2*np+1][1] = t[3];
            }
#pragma unroll
            for (int mi = 0; mi < 4; mi++)
#pragma unroll
                for (int nt = 0; nt < 4; nt++) {
                    mma16816(acc[mi][nt], af[mi], bf_[nt]);
                    mma16816(acc[mi][nt], af[mi], bg[nt]);
                    mma16816(acc[mi][nt], ag[mi], bf_[nt]);
                }
        }

        const bool diag = (kt == qt);
#pragma unroll
        for (int mi = 0; mi < 4; mi++)
#pragma unroll
            for (int hf = 0; hf < 2; hf++) {
                const int r = wm * 64 + mi * 16 + (lid >> 2) + hf * 8;
                float part = 0.f;
#pragma unroll
                for (int nt = 0; nt < 4; nt++) {
                    const int c = wn * 32 + nt * 8 + 2 * (lid & 3);
                    float e0 = exp_fast(acc[mi][nt][hf * 2 + 0]);
                    float e1 = exp_fast(acc[mi][nt][hf * 2 + 1]);
                    if (diag) {
                        if (c > r)     e0 = 0.f;
                        if (c + 1 > r) e1 = 0.f;
                    }
                    part += e0 + e1;
                    *(float2*)(out_w + wbase + (size_t)r * SS + kt * 128 + c) =
                        make_float2(e0, e1);
                }
                lsum[mi * 2 + hf] += part;
            }
        __syncthreads();
    }

#pragma unroll
    for (int i = 0; i < 8; i++) {
        lsum[i] += __shfl_xor_sync(0xffffffffu, lsum[i], 1);
        lsum[i] += __shfl_xor_sync(0xffffffffu, lsum[i], 2);
    }
    if ((lid & 3) == 0) {
#pragma unroll
        for (int mi = 0; mi < 4; mi++)
#pragma unroll
            for (int hf = 0; hf < 2; hf++)
                atomicAdd(&ls[wm * 64 + mi * 16 + (lid >> 2) + hf * 8],
                          lsum[mi * 2 + hf]);
    }
    __syncthreads();
    if (tid < 128) g_l[bh * SS + qt * 128 + tid] = ls[tid];
}

// ---- K3: HMMA P·V.  W = U*il written back; O = (U@V)*il -> bf16 hi/lo ------
// U tile converted to bf16 hi/lo in smem (A operand); V via ldmatrix.trans.
#define AV_UH 0
#define AV_UL 18432
#define AV_VH 36864
#define AV_VL 46080
#define AV_IL 55296
#define AVSM_BYTES 55808

__global__ void __launch_bounds__(256, 2)
mm_av_kernel(float* __restrict__ out_w)
{
    extern __shared__ char smp[];
    const uint32_t sm0 = smem_u32(smp);
    float* ils = (float*)(smp + AV_IL);

    const int qt = 15 - blockIdx.x;
    const int bh = blockIdx.y;
    const int b = bh >> 4, h = bh & 15;
    const int tid = threadIdx.x, wid = tid >> 5, lid = tid & 31;
    const int wm = wid >> 2, wn = wid & 3;
    const int lrow = lid & 15, lcol = (lid >> 4) * 8;

    if (tid < 128) ils[tid] = 1.0f / g_l[bh * SS + qt * 128 + tid];
    __syncthreads();

    float acc[4][2][4];
#pragma unroll
    for (int mi = 0; mi < 4; mi++)
#pragma unroll
        for (int nd = 0; nd < 2; nd++)
#pragma unroll
            for (int v = 0; v < 4; v++) acc[mi][nd][v] = 0.f;

    const size_t wbase = ((size_t)bh * SS + (size_t)qt * 128) * SS;
    const int nck = 2 * (qt + 1);
    const __nv_bfloat16* vh = g_qkvh + (size_t)(b * SS) * NQKV + 2 * EE + h * DD;
    const __nv_bfloat16* vl = g_qkvl + (size_t)(b * SS) * NQKV + 2 * EE + h * DD;

    const int urow0 = tid >> 4;        // 0..15
    const int ucol  = (tid & 15) * 4;  // 0..60

    for (int kc = 0; kc < nck; kc++) {
        // stage V tile (64 tok x 64 d, hi+lo) via cp.async
#pragma unroll
        for (int i = 0; i < 4; i++) {
            int g = tid + (i << 8);
            int arr = g >> 9, row = (g >> 3) & 63, q = g & 7;
            const __nv_bfloat16* s = (arr ? vl : vh) + (size_t)(kc * 64 + row) * NQKV + q * 8;
            CP16(sm0 + (arr ? AV_VL : AV_VH) + row * 144 + q * 16, s);
        }
        CPC();

        // U: load f32, write W=U*il back, convert U to bf16 hi/lo in smem
#pragma unroll
        for (int rs = 0; rs < 8; rs++) {
            const int r = urow0 + rs * 16;
            float* wrow = out_w + wbase + (size_t)r * SS + kc * 64 + ucol;
            float4 u = *(const float4*)wrow;
            const float il = ils[r];
            *(float4*)wrow = make_float4(u.x * il, u.y * il, u.z * il, u.w * il);
            float r0, r1;
            const uint32_t uo = (uint32_t)r * 144 + ucol * 2;
            *(__nv_bfloat162*)(smp + AV_UH + uo) = split_hi(u.x, u.y, r0, r1);
            *(__nv_bfloat162*)(smp + AV_UL + uo) =
                __halves2bfloat162(__float2bfloat16_rn(r0), __float2bfloat16_rn(r1));
            *(__nv_bfloat162*)(smp + AV_UH + uo + 4) = split_hi(u.z, u.w, r0, r1);
            *(__nv_bfloat162*)(smp + AV_UL + uo + 4) =
                __halves2bfloat162(__float2bfloat16_rn(r0), __float2bfloat16_rn(r1));
        }
        CPW(0);
        __syncthreads();

        // O += U(tile) @ V(tile)   (3-MMA bf16 emulation)
#pragma unroll
        for (int ks = 0; ks < 4; ks++) {
            uint32_t af[4][4], ag[4][4];
#pragma unroll
            for (int mi = 0; mi < 4; mi++) {
                uint32_t off = (uint32_t)(wm * 64 + mi * 16 + lrow) * 144 + (ks * 16 + lcol) * 2;
                ldx4(af[mi], sm0 + AV_UH + off);
                ldx4(ag[mi], sm0 + AV_UL + off);
            }
            uint32_t bh2[2][2], bl2[2][2], t[4];
            const int vrow = ks * 16 + (lid & 7) + ((lid >> 3) & 1) * 8;
            const int vcol = wn * 16 + ((lid >> 4) & 1) * 8;
            const uint32_t voff = (uint32_t)vrow * 144 + vcol * 2;
            ldx4t(t, sm0 + AV_VH + voff);
            bh2[0][0] = t[0]; bh2[0][1] = t[1]; bh2[1][0] = t[2]; bh2[1][1] = t[3];
            ldx4t(t, sm0 + AV_VL + voff);
            bl2[0][0] = t[0]; bl2[0][1] = t[1]; bl2[1][0] = t[2]; bl2[1][1] = t[3];
#pragma unroll
            for (int mi = 0; mi < 4; mi++)
#pragma unroll
                for (int nd = 0; nd < 2; nd++) {
                    mma16816(acc[mi][nd], af[mi], bh2[nd]);
                    mma16816(acc[mi][nd], af[mi], bl2[nd]);
                    mma16816(acc[mi][nd], ag[mi], bh2[nd]);
                }
        }
        __syncthreads();
    }

    // zero-fill fully masked chunks
    for (int kc = nck; kc < SS / 64; kc++) {
#pragma unroll
        for (int rs = 0; rs < 8; rs++) {
            const int r = urow0 + rs * 16;
            *(float4*)(out_w + wbase + (size_t)r * SS + kc * 64 + ucol) =
                make_float4(0.f, 0.f, 0.f, 0.f);
        }
    }

    // epilogue: O * il -> bf16 hi/lo attn-out
#pragma unroll
    for (int mi = 0; mi < 4; mi++)
#pragma unroll
        for (int hf = 0; hf < 2; hf++) {
            const int rloc = wm * 64 + mi * 16 + (lid >> 2) + hf * 8;
            const float il = ils[rloc];
            const size_t rowbase = (size_t)(b * SS + qt * 128 + rloc) * EE + h * DD;
#pragma unroll
            for (int nd = 0; nd < 2; nd++) {
                const int dcol = wn * 16 + nd * 8 + 2 * (lid & 3);
                float v0 = acc[mi][nd][hf * 2 + 0] * il;
                float v1 = acc[mi][nd][hf * 2 + 1] * il;
                float r0, r1;
                *(__nv_bfloat162*)(g_aoh + rowbase + dcol) = split_hi(v0, v1, r0, r1);
                *(__nv_bfloat162*)(g_aol + rowbase + dcol) =
                    __halves2bfloat162(__float2bfloat16_rn(r0), __float2bfloat16_rn(r1));
            }
        }
}

// ---------------------------------------------------------------------------
extern "C" void kernel_launch(void* const* d_in, const int* in_sizes, int n_in,
                              void* d_out, int out_size)
{
    const float* hidden = (const float*)d_in[0];
    const float* w_attn = (const float*)d_in[1];
    const float* b_attn = (const float*)d_in[2];
    const float* w_proj = (const float*)d_in[3];
    const float* b_proj = (const float*)d_in[4];

    float* out = (float*)d_out;
    float* out_attn = out;
    float* out_w = out + (size_t)MTOK * EE;

    void *p_qkvh, *p_qkvl, *p_hh, *p_hl, *p_wqTh, *p_wqTl, *p_wpTh, *p_wpTl, *p_aoh, *p_aol;
    cudaGetSymbolAddress(&p_qkvh, g_qkvh);
    cudaGetSymbolAddress(&p_qkvl, g_qkvl);
    cudaGetSymbolAddress(&p_hh,   g_hh);
    cudaGetSymbolAddress(&p_hl,   g_hl);
    cudaGetSymbolAddress(&p_wqTh, g_wqTh);
    cudaGetSymbolAddress(&p_wqTl, g_wqTl);
    cudaGetSymbolAddress(&p_wpTh, g_wpTh);
    cudaGetSymbolAddress(&p_wpTl, g_wpTl);
    cudaGetSymbolAddress(&p_aoh,  g_aoh);
    cudaGetSymbolAddress(&p_aol,  g_aol);

    cudaFuncSetAttribute(mm_gemm_kernel,   cudaFuncAttributeMaxDynamicSharedMemorySize, GSM_BYTES);
    cudaFuncSetAttribute(mm_scores_kernel, cudaFuncAttributeMaxDynamicSharedMemorySize, SSM_BYTES);
    cudaFuncSetAttribute(mm_av_kernel,     cudaFuncAttributeMaxDynamicSharedMemorySize, AVSM_BYTES);

    split_f32_kernel<<<(MTOK * EE) / 1024, 256>>>(hidden, (__nv_bfloat16*)p_hh, (__nv_bfloat16*)p_hl);
    transpose_split_kernel<<<dim3(NQKV / 32, EE / 32), dim3(32, 8)>>>(
        w_attn, (__nv_bfloat16*)p_wqTh, (__nv_bfloat16*)p_wqTl, NQKV, EE);
    transpose_split_kernel<<<dim3(EE / 32, EE / 32), dim3(32, 8)>>>(
        w_proj, (__nv_bfloat16*)p_wpTh, (__nv_bfloat16*)p_wpTl, EE, EE);

    // K1: QKV (HMMA, 3-stage) -> bf16 hi/lo (Q scaled 1/8)
    mm_gemm_kernel<<<dim3(NQKV / 128, MTOK / 128), 256, GSM_BYTES>>>(
        (const __nv_bfloat16*)p_hh, (const __nv_bfloat16*)p_hl,
        (const __nv_bfloat16*)p_wqTh, (const __nv_bfloat16*)p_wqTl,
        b_attn, (float*)0, (__nv_bfloat16*)p_qkvh, (__nv_bfloat16*)p_qkvl,
        NQKV, EE, 1);

    // K2: QK^T + exp -> U, row sums
    mm_scores_kernel<<<dim3(SS / 128, BB * HH), 256, SSM_BYTES>>>(out_w);

    // K3: W = U/l in place; O = U@V/l (HMMA)
    mm_av_kernel<<<dim3(SS / 128, BB * HH), 256, AVSM_BYTES>>>(out_w);

    // K4: projection (HMMA, 3-stage)
    mm_gemm_kernel<<<dim3(EE / 128, MTOK / 128), 256, GSM_BYTES>>>(
        (const __nv_bfloat16*)p_aoh, (const __nv_bfloat16*)p_aol,
        (const __nv_bfloat16*)p_wpTh, (const __nv_bfloat16*)p_wpTl,
        b_proj, out_attn, (__nv_bfloat16*)0, (__nv_bfloat16*)0,
        EE, EE, 0);
}